// round 2
// baseline (speedup 1.0000x reference)
#include <cuda_runtime.h>
#include <cuda_bf16.h>
#include <math.h>

// ---------------------------------------------------------------------------
// EBP_binaryNet forward:
//   m = tanh(w/2)  (== 2*sigmoid(w)-1)
//   L1: h1 = SQ2PI*(x @ m0 + th0)/sqrt(colsum(1-m0^2));  x1 = tanh(BN(h1))
//   L2: h2 = SQ2PI*(x1 @ m1 + th1)/sqrt(rowsum(1-m1^2)); x2 = tanh(BN(h2))
//   L3: h3 = SQ2PI*(x2 @ m3 + th1)/sqrt(rowsum(1-m3^2)); x4 = tanh(BN(h3))
//   out: hlast = x4 @ mlast + thlast; logp = log_softmax; loss; frac_correct
// BN = training-mode batch norm (batch mean, biased var, eps=1e-5), no affine.
// NOTE: kernel_launch is pure kernel launches (no runtime API calls) so the
// CUDA-graph capture sees only launch nodes. All scratch lives in __device__
// globals referenced directly from device code.
// ---------------------------------------------------------------------------

#define M_ROWS   65536
#define IN_DIM   784
#define H_DIM    512
#define D_OUT    10
#define SQ2PI    0.79788456f
#define BN_EPS   1e-5f

// ------------------------- device scratch (static) -------------------------
__device__ float g_m0[IN_DIM * H_DIM];
__device__ float g_m1[H_DIM * H_DIM];
__device__ float g_m3[H_DIM * H_DIM];
__device__ float g_mlast[H_DIM * D_OUT];
__device__ float g_scale[3][H_DIM];
__device__ float g_sum[3][H_DIM];
__device__ float g_sumsq[3][H_DIM];
__device__ float g_mean[3][H_DIM];
__device__ float g_rstd[3][H_DIM];
__device__ float g_hA[(size_t)M_ROWS * H_DIM];
__device__ float g_hB[(size_t)M_ROWS * H_DIM];
__device__ float g_loss[1];
__device__ int   g_correct[1];

// ------------------------- small prep kernels ------------------------------
__global__ void k_binarize_all(const float* __restrict__ w0, const float* __restrict__ w1,
                               const float* __restrict__ w3, const float* __restrict__ wlast)
{
    int i = blockIdx.x * blockDim.x + threadIdx.x;
    if (i < IN_DIM * H_DIM) g_m0[i] = tanhf(0.5f * w0[i]);
    if (i < H_DIM * H_DIM) {
        g_m1[i] = tanhf(0.5f * w1[i]);
        g_m3[i] = tanhf(0.5f * w3[i]);
    }
    if (i < H_DIM * D_OUT) g_mlast[i] = tanhf(0.5f * wlast[i]);
}

__global__ void k_zero_stats() {
    int i = blockIdx.x * blockDim.x + threadIdx.x;
    if (i < 3 * H_DIM) {
        (&g_sum[0][0])[i]   = 0.0f;
        (&g_sumsq[0][0])[i] = 0.0f;
    }
    if (i == 0) { g_loss[0] = 0.0f; g_correct[0] = 0; }
}

// scale[0][j] = SQ2PI / sqrt( sum_r (1 - m0[r][j]^2) )  (column sums of m0)
__global__ void k_diag_col0() {
    int j = blockIdx.x * blockDim.x + threadIdx.x;
    if (j >= H_DIM) return;
    float s = 0.0f;
    for (int r = 0; r < IN_DIM; r++) {
        float v = g_m0[r * H_DIM + j];
        s += 1.0f - v * v;
    }
    g_scale[0][j] = SQ2PI * rsqrtf(s);
}

// scale[L][r] = SQ2PI / sqrt( sum_c (1 - m[r][c]^2) )  (row sums), warp/row
template <int L>
__global__ void k_diag_row() {
    const float* m = (L == 1) ? g_m1 : g_m3;
    int warp = (blockIdx.x * blockDim.x + threadIdx.x) >> 5;
    int lane = threadIdx.x & 31;
    if (warp >= H_DIM) return;
    float s = 0.0f;
    #pragma unroll
    for (int t = 0; t < H_DIM / 32; t++) {
        float v = m[warp * H_DIM + t * 32 + lane];
        s += 1.0f - v * v;
    }
    #pragma unroll
    for (int o = 16; o; o >>= 1) s += __shfl_xor_sync(0xFFFFFFFFu, s, o);
    if (lane == 0) g_scale[L][warp] = SQ2PI * rsqrtf(s);
}

// ------------------------- main GEMM body ----------------------------------
// C[M,512] = epi( A' @ B ), A' = BNIN ? tanh((A-mean)*rstd) : A
// epi(v)[r][c] = (v + bias[c]) * scale[c]
// Tiles: 128x128x16, 256 threads, 8x8 per thread, double-buffered smem.
template <bool BNIN>
__device__ __forceinline__ void gemm_body(
    const float* __restrict__ A, const float* __restrict__ B,
    const float* __restrict__ bias, const float* __restrict__ scale,
    const float* __restrict__ mean, const float* __restrict__ rstd,
    float* __restrict__ C, int K)
{
    constexpr int N = H_DIM;
    __shared__ float As[2][16][128];
    __shared__ float Bs[2][16][128];

    const int tid = threadIdx.x;
    const int tx = tid & 15;
    const int ty = tid >> 4;
    const int rowA0 = blockIdx.y * 128;
    const int colB0 = blockIdx.x * 128;

    const int a_row = tid >> 2;   // + u*64
    const int a_c4  = tid & 3;
    const int b_kr  = tid >> 5;   // + u*8
    const int b_cc  = tid & 31;

    float acc[8][8] = {};
    float4 pa[2], pb[2];
    const int nk = K >> 4;

    // ---- prologue: load tile 0 into buffer 0 ----
    #pragma unroll
    for (int u = 0; u < 2; u++) {
        int row = a_row + u * 64;
        int kg = a_c4 * 4;
        float4 v = *reinterpret_cast<const float4*>(A + (size_t)(rowA0 + row) * K + kg);
        if (BNIN) {
            float4 mu = *reinterpret_cast<const float4*>(mean + kg);
            float4 rs = *reinterpret_cast<const float4*>(rstd + kg);
            v.x = tanhf((v.x - mu.x) * rs.x);
            v.y = tanhf((v.y - mu.y) * rs.y);
            v.z = tanhf((v.z - mu.z) * rs.z);
            v.w = tanhf((v.w - mu.w) * rs.w);
        }
        pa[u] = v;
    }
    #pragma unroll
    for (int u = 0; u < 2; u++) {
        int kr = b_kr + u * 8;
        pb[u] = *reinterpret_cast<const float4*>(B + (size_t)kr * N + colB0 + b_cc * 4);
    }
    #pragma unroll
    for (int u = 0; u < 2; u++) {
        int row = a_row + u * 64;
        As[0][a_c4 * 4 + 0][row] = pa[u].x;
        As[0][a_c4 * 4 + 1][row] = pa[u].y;
        As[0][a_c4 * 4 + 2][row] = pa[u].z;
        As[0][a_c4 * 4 + 3][row] = pa[u].w;
        *reinterpret_cast<float4*>(&Bs[0][b_kr + u * 8][b_cc * 4]) = pb[u];
    }
    __syncthreads();

    int cur = 0;
    for (int kt = 0; kt < nk; kt++) {
        if (kt + 1 < nk) {
            const int k0 = (kt + 1) * 16;
            #pragma unroll
            for (int u = 0; u < 2; u++) {
                int row = a_row + u * 64;
                int kg = k0 + a_c4 * 4;
                float4 v = *reinterpret_cast<const float4*>(A + (size_t)(rowA0 + row) * K + kg);
                if (BNIN) {
                    float4 mu = *reinterpret_cast<const float4*>(mean + kg);
                    float4 rs = *reinterpret_cast<const float4*>(rstd + kg);
                    v.x = tanhf((v.x - mu.x) * rs.x);
                    v.y = tanhf((v.y - mu.y) * rs.y);
                    v.z = tanhf((v.z - mu.z) * rs.z);
                    v.w = tanhf((v.w - mu.w) * rs.w);
                }
                pa[u] = v;
            }
            #pragma unroll
            for (int u = 0; u < 2; u++) {
                int kr = k0 + b_kr + u * 8;
                pb[u] = *reinterpret_cast<const float4*>(B + (size_t)kr * N + colB0 + b_cc * 4);
            }
        }

        #pragma unroll
        for (int kk = 0; kk < 16; kk++) {
            float4 a0 = *reinterpret_cast<const float4*>(&As[cur][kk][ty * 8]);
            float4 a1 = *reinterpret_cast<const float4*>(&As[cur][kk][ty * 8 + 4]);
            float4 b0 = *reinterpret_cast<const float4*>(&Bs[cur][kk][tx * 8]);
            float4 b1 = *reinterpret_cast<const float4*>(&Bs[cur][kk][tx * 8 + 4]);
            float ar[8] = {a0.x, a0.y, a0.z, a0.w, a1.x, a1.y, a1.z, a1.w};
            float br[8] = {b0.x, b0.y, b0.z, b0.w, b1.x, b1.y, b1.z, b1.w};
            #pragma unroll
            for (int i = 0; i < 8; i++)
                #pragma unroll
                for (int j = 0; j < 8; j++)
                    acc[i][j] = fmaf(ar[i], br[j], acc[i][j]);
        }

        if (kt + 1 < nk) {
            int nxt = cur ^ 1;
            #pragma unroll
            for (int u = 0; u < 2; u++) {
                int row = a_row + u * 64;
                As[nxt][a_c4 * 4 + 0][row] = pa[u].x;
                As[nxt][a_c4 * 4 + 1][row] = pa[u].y;
                As[nxt][a_c4 * 4 + 2][row] = pa[u].z;
                As[nxt][a_c4 * 4 + 3][row] = pa[u].w;
                *reinterpret_cast<float4*>(&Bs[nxt][b_kr + u * 8][b_cc * 4]) = pb[u];
            }
            __syncthreads();
            cur = nxt;
        }
    }

    // ---- epilogue: (acc + bias[c]) * scale[c] ----
    #pragma unroll
    for (int i = 0; i < 8; i++) {
        size_t r = (size_t)(rowA0 + ty * 8 + i);
        #pragma unroll
        for (int j = 0; j < 8; j += 4) {
            int c = colB0 + tx * 8 + j;
            float4 o;
            o.x = (acc[i][j + 0] + bias[c + 0]) * scale[c + 0];
            o.y = (acc[i][j + 1] + bias[c + 1]) * scale[c + 1];
            o.z = (acc[i][j + 2] + bias[c + 2]) * scale[c + 2];
            o.w = (acc[i][j + 3] + bias[c + 3]) * scale[c + 3];
            *reinterpret_cast<float4*>(C + r * N + c) = o;
        }
    }
}

// thin wrappers binding device-global buffers per layer
__global__ void __launch_bounds__(256, 2) k_gemm_l1(const float* __restrict__ x,
                                                    const float* __restrict__ th0) {
    gemm_body<false>(x, g_m0, th0, g_scale[0], nullptr, nullptr, g_hA, IN_DIM);
}
__global__ void __launch_bounds__(256, 2) k_gemm_l2(const float* __restrict__ th1) {
    gemm_body<true>(g_hA, g_m1, th1, g_scale[1], g_mean[0], g_rstd[0], g_hB, H_DIM);
}
__global__ void __launch_bounds__(256, 2) k_gemm_l3(const float* __restrict__ th1) {
    gemm_body<true>(g_hB, g_m3, th1, g_scale[2], g_mean[1], g_rstd[1], g_hA, H_DIM);
}

// ---------------------- column stats (sum, sumsq) --------------------------
template <int L>
__global__ void __launch_bounds__(256) k_colstats() {
    const float* H = (L == 2 || L == 0) ? g_hA : g_hB;
    const int col = threadIdx.x;
    const size_t base = (size_t)blockIdx.x * 128 * H_DIM;
    float s0 = 0.f, q0 = 0.f, s1 = 0.f, q1 = 0.f;
    #pragma unroll 4
    for (int r = 0; r < 128; r++) {
        float a = H[base + (size_t)r * H_DIM + col];
        float b = H[base + (size_t)r * H_DIM + col + 256];
        s0 += a; q0 = fmaf(a, a, q0);
        s1 += b; q1 = fmaf(b, b, q1);
    }
    atomicAdd(&g_sum[L][col], s0);
    atomicAdd(&g_sumsq[L][col], q0);
    atomicAdd(&g_sum[L][col + 256], s1);
    atomicAdd(&g_sumsq[L][col + 256], q1);
}

template <int L>
__global__ void k_finalize_stats() {
    int j = blockIdx.x * blockDim.x + threadIdx.x;
    if (j >= H_DIM) return;
    const float inv = 1.0f / (float)M_ROWS;
    float mu = g_sum[L][j] * inv;
    float var = g_sumsq[L][j] * inv - mu * mu;
    g_mean[L][j] = mu;
    g_rstd[L][j] = rsqrtf(var + BN_EPS);
}

// ---------------------- last layer + softmax + loss ------------------------
__global__ void __launch_bounds__(256) k_last(
    const float* __restrict__ thlast, const int* __restrict__ target,
    float* __restrict__ out_h, float* __restrict__ out_lp)
{
    __shared__ float msh[D_OUT][H_DIM];   // transposed: msh[c][k]
    __shared__ float mush[H_DIM];
    __shared__ float rsh[H_DIM];
    __shared__ float th[D_OUT];
    __shared__ float wloss[8];
    __shared__ int   wcorr[8];

    const int tid = threadIdx.x;
    for (int i = tid; i < H_DIM * D_OUT; i += 256) {
        int c = i / H_DIM, k = i - c * H_DIM;
        msh[c][k] = g_mlast[k * D_OUT + c];
    }
    for (int i = tid; i < H_DIM; i += 256) { mush[i] = g_mean[2][i]; rsh[i] = g_rstd[2][i]; }
    if (tid < D_OUT) th[tid] = thlast[tid];
    __syncthreads();

    const int warp = tid >> 5;
    const int lane = tid & 31;
    const int row = blockIdx.x * 8 + warp;
    const float* hrow = g_hA + (size_t)row * H_DIM;

    float acc[D_OUT] = {};
    #pragma unroll 4
    for (int t = 0; t < H_DIM / 32; t++) {
        int k = t * 32 + lane;
        float xv = tanhf((hrow[k] - mush[k]) * rsh[k]);
        #pragma unroll
        for (int c = 0; c < D_OUT; c++) acc[c] = fmaf(xv, msh[c][k], acc[c]);
    }
    #pragma unroll
    for (int c = 0; c < D_OUT; c++)
        #pragma unroll
        for (int o = 16; o; o >>= 1) acc[c] += __shfl_xor_sync(0xFFFFFFFFu, acc[c], o);

    if (lane == 0) {
        float lg[D_OUT];
        float mx = -1e30f;
        #pragma unroll
        for (int c = 0; c < D_OUT; c++) { lg[c] = acc[c] + th[c]; mx = fmaxf(mx, lg[c]); }
        float se = 0.f;
        #pragma unroll
        for (int c = 0; c < D_OUT; c++) se += expf(lg[c] - mx);
        float lse = mx + logf(se);
        int am = 0; float bm = lg[0];
        #pragma unroll
        for (int c = 1; c < D_OUT; c++) if (lg[c] > bm) { bm = lg[c]; am = c; }
        #pragma unroll
        for (int c = 0; c < D_OUT; c++) {
            out_h[(size_t)row * D_OUT + c]  = lg[c];
            out_lp[(size_t)row * D_OUT + c] = lg[c] - lse;
        }
        int tgt = target[row];
        wloss[warp] = -(lg[tgt] - lse);
        wcorr[warp] = (am == tgt) ? 1 : 0;
    }
    __syncthreads();
    if (tid == 0) {
        float ls = 0.f; int cc = 0;
        #pragma unroll
        for (int w = 0; w < 8; w++) { ls += wloss[w]; cc += wcorr[w]; }
        atomicAdd(&g_loss[0], ls);
        atomicAdd(&g_correct[0], cc);
    }
}

__global__ void k_finalize_out(float* __restrict__ out_tail)
{
    const float inv = 1.0f / (float)M_ROWS;
    out_tail[0] = g_loss[0] * inv;
    out_tail[1] = (float)g_correct[0] * inv;
}

// ---------------------------------------------------------------------------
extern "C" void kernel_launch(void* const* d_in, const int* in_sizes, int n_in,
                              void* d_out, int out_size)
{
    (void)in_sizes; (void)n_in; (void)out_size;
    const float* x      = (const float*)d_in[0];
    const int*   target = (const int*)d_in[1];
    const float* w0     = (const float*)d_in[2];
    const float* w1     = (const float*)d_in[3];
    // d_in[4] = w2 (unused by reference)
    const float* w3     = (const float*)d_in[5];
    const float* wlast  = (const float*)d_in[6];
    const float* th0    = (const float*)d_in[7];
    const float* th1    = (const float*)d_in[8];
    // d_in[9] = th2 (unused by reference)
    const float* thlast = (const float*)d_in[10];
    float* out = (float*)d_out;

    // --- prep: binarize weights, zero stats, diag scales ---
    k_binarize_all<<<(IN_DIM * H_DIM + 255) / 256, 256>>>(w0, w1, w3, wlast);
    k_zero_stats<<<(3 * H_DIM + 255) / 256, 256>>>();
    k_diag_col0<<<2, 256>>>();
    k_diag_row<1><<<64, 256>>>();
    k_diag_row<2><<<64, 256>>>();

    dim3 ggrid(H_DIM / 128, M_ROWS / 128);

    // --- layer 1: h1 = epi(x @ m0 + th0) ---
    k_gemm_l1<<<ggrid, 256>>>(x, th0);
    k_colstats<0><<<M_ROWS / 128, 256>>>();
    k_finalize_stats<0><<<2, 256>>>();

    // --- layer 2: h2 = epi(tanh(BN(h1)) @ m1 + th1) ---
    k_gemm_l2<<<ggrid, 256>>>(th1);
    k_colstats<1><<<M_ROWS / 128, 256>>>();
    k_finalize_stats<1><<<2, 256>>>();

    // --- layer 3: h3 = epi(tanh(BN(h2)) @ m3 + th1), th1 reused (faithful) ---
    k_gemm_l3<<<ggrid, 256>>>(th1);
    k_colstats<2><<<M_ROWS / 128, 256>>>();
    k_finalize_stats<2><<<2, 256>>>();

    // --- last layer: logits, log_softmax, loss, accuracy ---
    float* out_h  = out;
    float* out_lp = out + (size_t)M_ROWS * D_OUT;
    float* out_tl = out + (size_t)2 * M_ROWS * D_OUT;
    k_last<<<M_ROWS / 8, 256>>>(thlast, target, out_h, out_lp);
    k_finalize_out<<<1, 1>>>(out_tl);
}

// round 4
// speedup vs baseline: 1.8717x; 1.8717x over previous
#include <cuda_runtime.h>
#include <cuda_fp16.h>
#include <math.h>
#include <stdint.h>

// ---------------------------------------------------------------------------
// EBP_binaryNet forward with mma.sync (HMMA) fp16-split GEMMs:
//   A = Ah + Al (fp16 hi/lo), W^T = Bh + Bl -> D ~= Ah Bh + Al Bh + Ah Bl (fp32 acc)
// Target is plain sm_100 PTX: no tcgen05/TMEM. Uses ldmatrix + mma.sync + cp.async.
// ---------------------------------------------------------------------------

#define M_ROWS 65536
#define IN_DIM 784
#define K1PAD  832            // 26 * 32
#define H_DIM  512
#define D_OUT  10
#define SQ2PI  0.79788456f
#define BN_EPS 1e-5f

#define STAGE 32768           // Ah 8K | Al 8K | Bh 8K | Bl 8K
#define SMEM_TOTAL 65536

// ------------------------- device scratch ----------------------------------
__device__ __align__(128) __half g_xh[(size_t)M_ROWS * K1PAD];
__device__ __align__(128) __half g_xl[(size_t)M_ROWS * K1PAD];
__device__ __align__(128) __half g_ah[(size_t)M_ROWS * H_DIM];
__device__ __align__(128) __half g_al[(size_t)M_ROWS * H_DIM];
__device__ __align__(128) float  g_h[(size_t)M_ROWS * H_DIM];
__device__ __align__(128) __half g_w0h[H_DIM * K1PAD];   // [n][k]
__device__ __align__(128) __half g_w0l[H_DIM * K1PAD];
__device__ __align__(128) __half g_w1h[H_DIM * H_DIM];
__device__ __align__(128) __half g_w1l[H_DIM * H_DIM];
__device__ __align__(128) __half g_w3h[H_DIM * H_DIM];
__device__ __align__(128) __half g_w3l[H_DIM * H_DIM];
__device__ float g_mlast[H_DIM * D_OUT];
__device__ float g_scale[3][H_DIM];
__device__ float g_sum[3][H_DIM];
__device__ float g_sumsq[3][H_DIM];
__device__ float g_mean[3][H_DIM];
__device__ float g_rstd[3][H_DIM];
__device__ float g_loss[1];
__device__ int   g_correct[1];

// ------------------------- PTX helpers -------------------------------------
__device__ __forceinline__ uint32_t s2u(const void* p) {
    uint32_t a;
    asm("{ .reg .u64 t; cvta.to.shared.u64 t, %1; cvt.u32.u64 %0, t; }" : "=r"(a) : "l"(p));
    return a;
}
__device__ __forceinline__ void cp16(uint32_t s, const void* g) {
    asm volatile("cp.async.cg.shared.global [%0], [%1], 16;" :: "r"(s), "l"(g));
}
#define CP_COMMIT() asm volatile("cp.async.commit_group;" ::: "memory")
#define CP_WAIT(n)  asm volatile("cp.async.wait_group %0;" :: "n"(n) : "memory")

__device__ __forceinline__ void ldsm4(uint32_t a, uint32_t* r) {
    asm volatile("ldmatrix.sync.aligned.m8n8.x4.shared.b16 {%0,%1,%2,%3}, [%4];"
                 : "=r"(r[0]), "=r"(r[1]), "=r"(r[2]), "=r"(r[3]) : "r"(a));
}
__device__ __forceinline__ void mma16816(float* d, const uint32_t* a, const uint32_t* b) {
    asm volatile(
        "mma.sync.aligned.m16n8k16.row.col.f32.f16.f16.f32 "
        "{%0,%1,%2,%3},{%4,%5,%6,%7},{%8,%9},{%0,%1,%2,%3};"
        : "+f"(d[0]), "+f"(d[1]), "+f"(d[2]), "+f"(d[3])
        : "r"(a[0]), "r"(a[1]), "r"(a[2]), "r"(a[3]), "r"(b[0]), "r"(b[1]));
}

// swizzled byte offset of (row, 16B-unit) inside a 128x32-half tile (64B rows)
__device__ __forceinline__ uint32_t swoff(int r, int u) {
    return (uint32_t)(r * 64 + ((u ^ ((r >> 1) & 3)) * 16));
}

// ------------------------- split helpers -----------------------------------
__device__ __forceinline__ void split2(float v, __half& hi, __half& lo) {
    hi = __float2half(v);
    lo = __float2half(v - __half2float(hi));
}

// ------------------------- prep kernels ------------------------------------
__global__ void k_prep_w0(const float* __restrict__ w0) {
    int n = blockIdx.x;
    for (int k = threadIdx.x; k < K1PAD; k += 256) {
        float m = (k < IN_DIM) ? tanhf(0.5f * w0[k * H_DIM + n]) : 0.0f;
        __half hi, lo; split2(m, hi, lo);
        g_w0h[n * K1PAD + k] = hi;
        g_w0l[n * K1PAD + k] = lo;
    }
}
__global__ void k_prep_w13(const float* __restrict__ w1, const float* __restrict__ w3) {
    int n = blockIdx.x;
    for (int k = threadIdx.x; k < H_DIM; k += 256) {
        float m1v = tanhf(0.5f * w1[k * H_DIM + n]);
        float m3v = tanhf(0.5f * w3[k * H_DIM + n]);
        __half hi, lo;
        split2(m1v, hi, lo); g_w1h[n * H_DIM + k] = hi; g_w1l[n * H_DIM + k] = lo;
        split2(m3v, hi, lo); g_w3h[n * H_DIM + k] = hi; g_w3l[n * H_DIM + k] = lo;
    }
}
__global__ void k_prep_mlast(const float* __restrict__ wlast) {
    int i = blockIdx.x * blockDim.x + threadIdx.x;
    if (i < H_DIM * D_OUT) g_mlast[i] = tanhf(0.5f * wlast[i]);
}
__global__ void k_zero_stats() {
    int i = blockIdx.x * blockDim.x + threadIdx.x;
    if (i < 3 * H_DIM) { (&g_sum[0][0])[i] = 0.0f; (&g_sumsq[0][0])[i] = 0.0f; }
    if (i == 0) { g_loss[0] = 0.0f; g_correct[0] = 0; }
}
__global__ void k_diag_col0(const float* __restrict__ w0) {
    int j = blockIdx.x * blockDim.x + threadIdx.x;
    if (j >= H_DIM) return;
    float s = 0.0f;
    for (int k = 0; k < IN_DIM; k++) {
        float v = tanhf(0.5f * w0[k * H_DIM + j]);
        s += 1.0f - v * v;
    }
    g_scale[0][j] = SQ2PI * rsqrtf(s);
}
template <int L>
__global__ void k_diag_row(const float* __restrict__ w) {
    int row = (blockIdx.x * blockDim.x + threadIdx.x) >> 5;
    int lane = threadIdx.x & 31;
    if (row >= H_DIM) return;
    float s = 0.0f;
    #pragma unroll
    for (int t = 0; t < H_DIM / 32; t++) {
        float v = tanhf(0.5f * w[row * H_DIM + t * 32 + lane]);
        s += 1.0f - v * v;
    }
    #pragma unroll
    for (int o = 16; o; o >>= 1) s += __shfl_xor_sync(0xFFFFFFFFu, s, o);
    if (lane == 0) g_scale[L][row] = SQ2PI * rsqrtf(s);
}
__global__ void k_split_x(const float* __restrict__ x) {
    int row = blockIdx.x;
    const float2* xr = reinterpret_cast<const float2*>(x + (size_t)row * IN_DIM);
    __half2* oh = reinterpret_cast<__half2*>(g_xh + (size_t)row * K1PAD);
    __half2* ol = reinterpret_cast<__half2*>(g_xl + (size_t)row * K1PAD);
    for (int p = threadIdx.x; p < K1PAD / 2; p += 256) {
        float2 v = (2 * p < IN_DIM) ? xr[p] : make_float2(0.f, 0.f);
        __half h0, l0, h1, l1;
        split2(v.x, h0, l0); split2(v.y, h1, l1);
        oh[p] = __halves2half2(h0, h1);
        ol[p] = __halves2half2(l0, l1);
    }
}
template <int L>
__global__ void k_split_act() {
    int row = blockIdx.x;
    int p = threadIdx.x;   // 256 pairs = 512 cols
    const float2* hr = reinterpret_cast<const float2*>(g_h + (size_t)row * H_DIM);
    const float2* mu = reinterpret_cast<const float2*>(g_mean[L]);
    const float2* rs = reinterpret_cast<const float2*>(g_rstd[L]);
    float2 v = hr[p], m = mu[p], r = rs[p];
    float a0 = tanhf((v.x - m.x) * r.x);
    float a1 = tanhf((v.y - m.y) * r.y);
    __half h0, l0, h1, l1;
    split2(a0, h0, l0); split2(a1, h1, l1);
    reinterpret_cast<__half2*>(g_ah + (size_t)row * H_DIM)[p] = __halves2half2(h0, h1);
    reinterpret_cast<__half2*>(g_al + (size_t)row * H_DIM)[p] = __halves2half2(l0, l1);
}

// ------------------------- mma.sync GEMM -----------------------------------
// C[128 x 128 per CTA] = ((Ah+Al) @ (Bh+Bl)^T + bias[c]) * scale[c]
// A [M][K] row-major halves, B [N][K] row-major halves (i.e. W transposed).
// 256 threads = 8 warps (4m x 2n), warp tile 32x64, K-chunk 32, 2-stage cp.async.
template <int K, int NK>
__device__ __forceinline__ void gemm_mma(
    const __half* __restrict__ Ah, const __half* __restrict__ Al,
    const __half* __restrict__ Bh, const __half* __restrict__ Bl,
    const float* __restrict__ bias, const float* __restrict__ scale,
    float* __restrict__ C)
{
    extern __shared__ __align__(128) char smem[];
    const uint32_t sbase = s2u(smem);
    const int tid = threadIdx.x, lane = tid & 31, wid = tid >> 5;
    const int rowA0 = blockIdx.y * 128, colB0 = blockIdx.x * 128;
    const int wm = wid >> 1, wn = wid & 1;

    // --- cp.async source setup: thread handles row r, 16B unit pair hs ---
    const int r  = tid >> 1;
    const int hs = tid & 1;
    const __half* pAh = Ah + (size_t)(rowA0 + r) * K + hs * 16;
    const __half* pAl = Al + (size_t)(rowA0 + r) * K + hs * 16;
    const __half* pBh = Bh + (size_t)(colB0 + r) * K + hs * 16;
    const __half* pBl = Bl + (size_t)(colB0 + r) * K + hs * 16;
    const uint32_t so0 = swoff(r, hs * 2);
    const uint32_t so1 = swoff(r, hs * 2 + 1);

    // --- ldmatrix address offsets (tile-relative) ---
    const int ar = wm * 32 + (lane & 7) + ((lane >> 3) & 1) * 8;
    const int au = lane >> 4;
    const int br = wn * 64 + (lane & 7) + (lane >> 4) * 8;
    const int bu = (lane >> 3) & 1;
    uint32_t a_off[2][2], b_off[4][2];
    #pragma unroll
    for (int mt = 0; mt < 2; mt++)
        #pragma unroll
        for (int ks = 0; ks < 2; ks++) a_off[mt][ks] = swoff(ar + mt * 16, au + 2 * ks);
    #pragma unroll
    for (int nb = 0; nb < 4; nb++)
        #pragma unroll
        for (int ks = 0; ks < 2; ks++) b_off[nb][ks] = swoff(br + nb * 16, bu + 2 * ks);

    float acc[2][8][4] = {};

    // --- pipeline ---
    auto issue = [&](int ch) {
        const uint32_t sb = sbase + (ch & 1) * STAGE;
        const size_t k0 = (size_t)ch * 32;
        cp16(sb +         so0, pAh + k0);  cp16(sb +         so1, pAh + k0 + 8);
        cp16(sb +  8192 + so0, pAl + k0);  cp16(sb +  8192 + so1, pAl + k0 + 8);
        cp16(sb + 16384 + so0, pBh + k0);  cp16(sb + 16384 + so1, pBh + k0 + 8);
        cp16(sb + 24576 + so0, pBl + k0);  cp16(sb + 24576 + so1, pBl + k0 + 8);
    };

    issue(0); CP_COMMIT();
    for (int ch = 0; ch < NK; ch++) {
        if (ch + 1 < NK) { issue(ch + 1); CP_COMMIT(); CP_WAIT(1); }
        else             { CP_WAIT(0); }
        __syncthreads();

        const uint32_t sb = sbase + (ch & 1) * STAGE;
        #pragma unroll
        for (int ks = 0; ks < 2; ks++) {
            uint32_t ah[2][4], al[2][4];
            ldsm4(sb + a_off[0][ks], ah[0]);
            ldsm4(sb + a_off[1][ks], ah[1]);
            ldsm4(sb + 8192 + a_off[0][ks], al[0]);
            ldsm4(sb + 8192 + a_off[1][ks], al[1]);
            #pragma unroll
            for (int nb = 0; nb < 4; nb++) {
                uint32_t bh[4], bl[4];
                ldsm4(sb + 16384 + b_off[nb][ks], bh);
                ldsm4(sb + 24576 + b_off[nb][ks], bl);
                #pragma unroll
                for (int mt = 0; mt < 2; mt++) {
                    mma16816(acc[mt][2 * nb],     ah[mt], bh);
                    mma16816(acc[mt][2 * nb],     al[mt], bh);
                    mma16816(acc[mt][2 * nb],     ah[mt], bl);
                    mma16816(acc[mt][2 * nb + 1], ah[mt], bh + 2);
                    mma16816(acc[mt][2 * nb + 1], al[mt], bh + 2);
                    mma16816(acc[mt][2 * nb + 1], ah[mt], bl + 2);
                }
            }
        }
        __syncthreads();
    }

    // --- epilogue: (acc + bias[c]) * scale[c] -> C fp32 ---
    #pragma unroll
    for (int mt = 0; mt < 2; mt++) {
        const int row0 = rowA0 + wm * 32 + mt * 16 + (lane >> 2);
        #pragma unroll
        for (int nt = 0; nt < 8; nt++) {
            const int col = colB0 + wn * 64 + nt * 8 + 2 * (lane & 3);
            const float b0 = __ldg(bias + col),     s0 = __ldg(scale + col);
            const float b1 = __ldg(bias + col + 1), s1 = __ldg(scale + col + 1);
            float2 o0, o1;
            o0.x = (acc[mt][nt][0] + b0) * s0;
            o0.y = (acc[mt][nt][1] + b1) * s1;
            o1.x = (acc[mt][nt][2] + b0) * s0;
            o1.y = (acc[mt][nt][3] + b1) * s1;
            *reinterpret_cast<float2*>(C + (size_t)row0 * H_DIM + col)       = o0;
            *reinterpret_cast<float2*>(C + (size_t)(row0 + 8) * H_DIM + col) = o1;
        }
    }
}

__global__ void __launch_bounds__(256, 2) k_gemm1(const float* __restrict__ th0) {
    gemm_mma<K1PAD, K1PAD / 32>(g_xh, g_xl, g_w0h, g_w0l, th0, g_scale[0], g_h);
}
__global__ void __launch_bounds__(256, 2) k_gemm2(const float* __restrict__ th1) {
    gemm_mma<H_DIM, H_DIM / 32>(g_ah, g_al, g_w1h, g_w1l, th1, g_scale[1], g_h);
}
__global__ void __launch_bounds__(256, 2) k_gemm3(const float* __restrict__ th1) {
    gemm_mma<H_DIM, H_DIM / 32>(g_ah, g_al, g_w3h, g_w3l, th1, g_scale[2], g_h);
}

// ---------------------- column stats (sum, sumsq) --------------------------
template <int L>
__global__ void __launch_bounds__(256) k_colstats() {
    const int col = threadIdx.x;
    const size_t base = (size_t)blockIdx.x * 128 * H_DIM;
    float s0 = 0.f, q0 = 0.f, s1 = 0.f, q1 = 0.f;
    #pragma unroll 4
    for (int r = 0; r < 128; r++) {
        float a = g_h[base + (size_t)r * H_DIM + col];
        float b = g_h[base + (size_t)r * H_DIM + col + 256];
        s0 += a; q0 = fmaf(a, a, q0);
        s1 += b; q1 = fmaf(b, b, q1);
    }
    atomicAdd(&g_sum[L][col], s0);
    atomicAdd(&g_sumsq[L][col], q0);
    atomicAdd(&g_sum[L][col + 256], s1);
    atomicAdd(&g_sumsq[L][col + 256], q1);
}
template <int L>
__global__ void k_finalize_stats() {
    int j = blockIdx.x * blockDim.x + threadIdx.x;
    if (j >= H_DIM) return;
    const float inv = 1.0f / (float)M_ROWS;
    float mu = g_sum[L][j] * inv;
    float var = g_sumsq[L][j] * inv - mu * mu;
    g_mean[L][j] = mu;
    g_rstd[L][j] = rsqrtf(var + BN_EPS);
}

// ---------------------- last layer + softmax + loss ------------------------
__global__ void __launch_bounds__(256) k_last(
    const float* __restrict__ thlast, const int* __restrict__ target,
    float* __restrict__ out_h, float* __restrict__ out_lp)
{
    __shared__ float msh[D_OUT][H_DIM];
    __shared__ float mush[H_DIM];
    __shared__ float rsh[H_DIM];
    __shared__ float th[D_OUT];
    __shared__ float wloss[8];
    __shared__ int   wcorr[8];

    const int tid = threadIdx.x;
    for (int i = tid; i < H_DIM * D_OUT; i += 256) {
        int c = i / H_DIM, k = i - c * H_DIM;
        msh[c][k] = g_mlast[k * D_OUT + c];
    }
    for (int i = tid; i < H_DIM; i += 256) { mush[i] = g_mean[2][i]; rsh[i] = g_rstd[2][i]; }
    if (tid < D_OUT) th[tid] = thlast[tid];
    __syncthreads();

    const int warp = tid >> 5;
    const int lane = tid & 31;
    const int row = blockIdx.x * 8 + warp;
    const float* hrow = g_h + (size_t)row * H_DIM;

    float acc[D_OUT] = {};
    #pragma unroll 4
    for (int t = 0; t < H_DIM / 32; t++) {
        int k = t * 32 + lane;
        float xv = tanhf((hrow[k] - mush[k]) * rsh[k]);
        #pragma unroll
        for (int c = 0; c < D_OUT; c++) acc[c] = fmaf(xv, msh[c][k], acc[c]);
    }
    #pragma unroll
    for (int c = 0; c < D_OUT; c++)
        #pragma unroll
        for (int o = 16; o; o >>= 1) acc[c] += __shfl_xor_sync(0xFFFFFFFFu, acc[c], o);

    if (lane == 0) {
        float lg[D_OUT];
        float mx = -1e30f;
        #pragma unroll
        for (int c = 0; c < D_OUT; c++) { lg[c] = acc[c] + th[c]; mx = fmaxf(mx, lg[c]); }
        float se = 0.f;
        #pragma unroll
        for (int c = 0; c < D_OUT; c++) se += expf(lg[c] - mx);
        float lse = mx + logf(se);
        int am = 0; float bm = lg[0];
        #pragma unroll
        for (int c = 1; c < D_OUT; c++) if (lg[c] > bm) { bm = lg[c]; am = c; }
        #pragma unroll
        for (int c = 0; c < D_OUT; c++) {
            out_h[(size_t)row * D_OUT + c]  = lg[c];
            out_lp[(size_t)row * D_OUT + c] = lg[c] - lse;
        }
        int tgt = target[row];
        wloss[warp] = -(lg[tgt] - lse);
        wcorr[warp] = (am == tgt) ? 1 : 0;
    }
    __syncthreads();
    if (tid == 0) {
        float ls = 0.f; int cc = 0;
        #pragma unroll
        for (int w = 0; w < 8; w++) { ls += wloss[w]; cc += wcorr[w]; }
        atomicAdd(&g_loss[0], ls);
        atomicAdd(&g_correct[0], cc);
    }
}
__global__ void k_finalize_out(float* __restrict__ out_tail) {
    const float inv = 1.0f / (float)M_ROWS;
    out_tail[0] = g_loss[0] * inv;
    out_tail[1] = (float)g_correct[0] * inv;
}

// ---------------------------------------------------------------------------
extern "C" void kernel_launch(void* const* d_in, const int* in_sizes, int n_in,
                              void* d_out, int out_size)
{
    (void)in_sizes; (void)n_in; (void)out_size;
    const float* x      = (const float*)d_in[0];
    const int*   target = (const int*)d_in[1];
    const float* w0     = (const float*)d_in[2];
    const float* w1     = (const float*)d_in[3];
    const float* w3     = (const float*)d_in[5];
    const float* wlast  = (const float*)d_in[6];
    const float* th0    = (const float*)d_in[7];
    const float* th1    = (const float*)d_in[8];
    const float* thlast = (const float*)d_in[10];
    float* out = (float*)d_out;

    cudaFuncSetAttribute(k_gemm1, cudaFuncAttributeMaxDynamicSharedMemorySize, SMEM_TOTAL);
    cudaFuncSetAttribute(k_gemm2, cudaFuncAttributeMaxDynamicSharedMemorySize, SMEM_TOTAL);
    cudaFuncSetAttribute(k_gemm3, cudaFuncAttributeMaxDynamicSharedMemorySize, SMEM_TOTAL);

    // --- prep ---
    k_prep_w0<<<H_DIM, 256>>>(w0);
    k_prep_w13<<<H_DIM, 256>>>(w1, w3);
    k_prep_mlast<<<(H_DIM * D_OUT + 255) / 256, 256>>>(wlast);
    k_zero_stats<<<(3 * H_DIM + 255) / 256, 256>>>();
    k_diag_col0<<<2, 256>>>(w0);
    k_diag_row<1><<<64, 256>>>(w1);
    k_diag_row<2><<<64, 256>>>(w3);
    k_split_x<<<M_ROWS, 256>>>(x);

    dim3 g2(H_DIM / 128, M_ROWS / 128);

    // --- layer 1 ---
    k_gemm1<<<g2, 256, SMEM_TOTAL>>>(th0);
    k_colstats<0><<<M_ROWS / 128, 256>>>();
    k_finalize_stats<0><<<2, 256>>>();
    k_split_act<0><<<M_ROWS, 256>>>();

    // --- layer 2 ---
    k_gemm2<<<g2, 256, SMEM_TOTAL>>>(th1);
    k_colstats<1><<<M_ROWS / 128, 256>>>();
    k_finalize_stats<1><<<2, 256>>>();
    k_split_act<1><<<M_ROWS, 256>>>();

    // --- layer 3 (th1 reused, faithful to reference) ---
    k_gemm3<<<g2, 256, SMEM_TOTAL>>>(th1);
    k_colstats<2><<<M_ROWS / 128, 256>>>();
    k_finalize_stats<2><<<2, 256>>>();

    // --- last layer ---
    float* out_h  = out;
    float* out_lp = out + (size_t)M_ROWS * D_OUT;
    float* out_tl = out + (size_t)2 * M_ROWS * D_OUT;
    k_last<<<M_ROWS / 8, 256>>>(thlast, target, out_h, out_lp);
    k_finalize_out<<<1, 1>>>(out_tl);
}